// round 9
// baseline (speedup 1.0000x reference)
#include <cuda_runtime.h>
#include <cstdint>

#define B_  2
#define S_  2048
#define H_  1024
#define NH  16
#define HD  64
#define BS_ (B_ * S_)                       // 4096
#define OUT_ELEMS ((size_t)B_ * S_ * H_)    // 4194304
#define AW_ELEMS  ((size_t)B_ * NH * S_ * S_)  // 134217728

typedef unsigned long long u64t;

// ---------- scratch (device globals: no allocation allowed) ----------
__device__ float g_qp[BS_ * H_];
__device__ float g_kp[BS_ * H_];
__device__ float g_vp[BS_ * H_];
__device__ float g_x [BS_ * H_];

// ---------- packed f32x2 helpers (sm_103a FFMA2/FADD2 path, PTX-only) ----------
__device__ __forceinline__ void ffma2(u64t& d, u64t a, u64t b) {
    asm("fma.rn.f32x2 %0, %1, %2, %0;" : "+l"(d) : "l"(a), "l"(b));
}
__device__ __forceinline__ u64t add2(u64t a, u64t b) {
    u64t d; asm("add.rn.f32x2 %0, %1, %2;" : "=l"(d) : "l"(a), "l"(b)); return d;
}
__device__ __forceinline__ u64t pk2(float x, float y) {
    u64t r; asm("mov.b64 %0, {%1, %2};" : "=l"(r) : "f"(x), "f"(y)); return r;
}
__device__ __forceinline__ void upk2(u64t v, float& x, float& y) {
    asm("mov.b64 {%0, %1}, %2;" : "=f"(x), "=f"(y) : "l"(v));
}

// ---------- cp.async helpers ----------
__device__ __forceinline__ void cpasync16(uint32_t dst_smem, const void* src) {
    asm volatile("cp.async.cg.shared.global [%0], [%1], 16;"
                 :: "r"(dst_smem), "l"(src) : "memory");
}
__device__ __forceinline__ void cpasync_commit() {
    asm volatile("cp.async.commit_group;" ::: "memory");
}
__device__ __forceinline__ void cpasync_wait0() {
    asm volatile("cp.async.wait_group 0;" ::: "memory");
}
__device__ __forceinline__ uint32_t smem_u32(const void* p) {
    return (uint32_t)__cvta_generic_to_shared(p);
}

// =====================================================================
// GEMM: C[M,N] = A[M,K] @ W[N,K]^T   (torch Linear, bias=False)
// 128x128 tile, BK=16, 256 threads, 8x8 micro-tile, f32x2 accumulators
// packed over column pairs. K-major smem, A duplicated ({a,a}).
// DOUBLE-BUFFERED: LDG(next) register-staged before compute(cur),
// STS(next) after compute, one barrier per k-iter.
// Fill mapping fr=tid&63 (lane-fast rows) -> conflict-free STS.
// blockIdx.z selects one of up to 3 independent (A,W,C) problems.
// =====================================================================
#define TM 128
#define TN 128
#define TKK 16
#define ASD_STRIDE 130          // float2 units per k-slice row dim
#define BS_STRIDE  136          // float units; 544B = 34*16 keeps LDS.128 align
#define GEMM_SMEM_A (2 * TKK * ASD_STRIDE * 8)          // 33280 B
#define GEMM_SMEM_B (2 * TKK * BS_STRIDE * 4)           // 17408 B
#define GEMM_SMEM   (GEMM_SMEM_A + GEMM_SMEM_B)         // 50688 B

extern __shared__ char dynsm[];

__global__ __launch_bounds__(256, 2) void gemm_xwT(
    const float* __restrict__ A0, const float* __restrict__ W0, float* __restrict__ C0,
    const float* __restrict__ A1, const float* __restrict__ W1, float* __restrict__ C1,
    const float* __restrict__ A2, const float* __restrict__ W2, float* __restrict__ C2,
    int M, int N, int K)
{
    const float* A; const float* W; float* C;
    if (blockIdx.z == 0)      { A = A0; W = W0; C = C0; }
    else if (blockIdx.z == 1) { A = A1; W = W1; C = C1; }
    else                      { A = A2; W = W2; C = C2; }

    float2* Asd = reinterpret_cast<float2*>(dynsm);                 // [2][TKK][130]
    float*  Bs  = reinterpret_cast<float*>(dynsm + GEMM_SMEM_A);    // [2][TKK][136]

    const int tid = threadIdx.x;
    const int tx = tid & 15;    // row set: rows tx, tx+16, ..., tx+112
    const int ty = tid >> 4;    // col block: cols ty*8 .. ty*8+7
    const int rowBase = blockIdx.y * TM;
    const int colBase = blockIdx.x * TN;

    u64t acc[8][4];
#pragma unroll
    for (int r = 0; r < 8; r++)
#pragma unroll
        for (int c = 0; c < 4; c++) acc[r][c] = 0ull;

    // fill mapping: lanes sweep rows (conflict-free STS), fk per thread-quad
    const int fr = tid & 63;          // fill row 0..63 (x2 halves)
    const int fk = (tid >> 6) * 4;    // fill k quad 0,4,8,12

    // ---- prologue: stage k-chunk 0 in registers ----
    float4 aS[2], wS[2];
#pragma unroll
    for (int l = 0; l < 2; l++) {
        int row = fr + 64 * l;
        aS[l] = *reinterpret_cast<const float4*>(&A[(size_t)(rowBase + row) * K + fk]);
        wS[l] = *reinterpret_cast<const float4*>(&W[(size_t)(colBase + row) * K + fk]);
    }

    const int NIT = K / TKK;
    for (int kt = 0; kt < NIT; kt++) {
        const int buf = kt & 1;

        // ---- store staged chunk into buffer ----
#pragma unroll
        for (int l = 0; l < 2; l++) {
            int row = fr + 64 * l;
            float2* ap = &Asd[(size_t)(buf * TKK + fk) * ASD_STRIDE + row];
            ap[0 * ASD_STRIDE] = make_float2(aS[l].x, aS[l].x);
            ap[1 * ASD_STRIDE] = make_float2(aS[l].y, aS[l].y);
            ap[2 * ASD_STRIDE] = make_float2(aS[l].z, aS[l].z);
            ap[3 * ASD_STRIDE] = make_float2(aS[l].w, aS[l].w);
            float* bp = &Bs[(size_t)(buf * TKK + fk) * BS_STRIDE + row];
            bp[0 * BS_STRIDE] = wS[l].x;
            bp[1 * BS_STRIDE] = wS[l].y;
            bp[2 * BS_STRIDE] = wS[l].z;
            bp[3 * BS_STRIDE] = wS[l].w;
        }
        __syncthreads();

        // ---- prefetch next chunk into registers (spans the compute below) ----
        if (kt + 1 < NIT) {
            int k0 = (kt + 1) * TKK;
#pragma unroll
            for (int l = 0; l < 2; l++) {
                int row = fr + 64 * l;
                aS[l] = *reinterpret_cast<const float4*>(&A[(size_t)(rowBase + row) * K + k0 + fk]);
                wS[l] = *reinterpret_cast<const float4*>(&W[(size_t)(colBase + row) * K + k0 + fk]);
            }
        }

        // ---- compute on current buffer ----
#pragma unroll
        for (int k = 0; k < TKK; k++) {
            u64t ad[8];
#pragma unroll
            for (int r = 0; r < 8; r++)
                ad[r] = *reinterpret_cast<const u64t*>(
                    &Asd[(size_t)(buf * TKK + k) * ASD_STRIDE + tx + 16 * r]);
            u64t bv[4];
            const ulonglong2* bp = reinterpret_cast<const ulonglong2*>(
                &Bs[(size_t)(buf * TKK + k) * BS_STRIDE + ty * 8]);
#pragma unroll
            for (int h = 0; h < 2; h++) { ulonglong2 t = bp[h]; bv[2*h] = t.x; bv[2*h+1] = t.y; }
#pragma unroll
            for (int r = 0; r < 8; r++)
#pragma unroll
                for (int c = 0; c < 4; c++) ffma2(acc[r][c], ad[r], bv[c]);
        }
    }

    // ---- epilogue: acc[r][c] already holds {C[..,2c], C[..,2c+1]} ----
#pragma unroll
    for (int r = 0; r < 8; r++) {
        int row = rowBase + tx + 16 * r;
        float* cp = &C[(size_t)row * N + colBase + ty * 8];
#pragma unroll
        for (int h = 0; h < 2; h++) {
            float x0, y0, x1, y1;
            upk2(acc[r][2*h], x0, y0); upk2(acc[r][2*h+1], x1, y1);
            *reinterpret_cast<float4*>(cp + 4*h) = make_float4(x0, y0, x1, y1);
        }
    }
}

// =====================================================================
// Fused attention (per head, raw-reshape layout => contiguous [2048,64]).
// 128 threads = 128 query rows per block. Single pass (scores bounded,
// |s| < ~3 -> no running max); writes UNNORMALIZED exp to attn_weight
// via an smem-staged COALESCED store path (direct per-row STG.32 would
// hit 32 lines/warp-instr and L1-throttle the kernel), accumulates l and
// p*V. Epilogue then normalizes this block's own 128 aw rows in place,
// overlapping that DRAM traffic with other blocks' compute.
// All aw traffic uses .cs (evict-first) hints: the aw stream has no L2
// reuse, and default policy would evict the K/V working set that every
// resident block re-reads each tile.
// K/V tiles double-buffered via cp.async (.cg: no L1 reuse for K/V).
// =====================================================================
#define ATM 128
#define ATJ 64
#define PS_STRIDE 65                              // floats; pad kills STS conflicts
#define ATT_TILE_B (ATJ * HD * 4)                 // 16384 B per matrix per buf
#define ATT_KV_B   (4 * ATT_TILE_B)               // 65536 B
#define ATT_PS_B   (ATM * PS_STRIDE * 4)          // 33280 B
#define ATT_SMEM   (ATT_KV_B + ATT_PS_B)          // 98816 B

__global__ __launch_bounds__(128) void attn_kernel(
    const float* __restrict__ qp, const float* __restrict__ kp,
    const float* __restrict__ vp, float* __restrict__ aw,
    float* __restrict__ xout)
{
    float* Ks = reinterpret_cast<float*>(dynsm);                    // [2][ATJ][HD]
    float* Vs = reinterpret_cast<float*>(dynsm + 2 * ATT_TILE_B);   // [2][ATJ][HD]
    float* Ps = reinterpret_cast<float*>(dynsm + ATT_KV_B);         // [ATM][65]

    const int tid = threadIdx.x;
    const int bn = blockIdx.y;            // b*16 + n
    const int b  = bn >> 4;
    const int n  = bn & 15;
    const size_t headoff = (size_t)b * S_ * H_ + (size_t)n * (S_ / NH) * H_;
    const float* Q  = qp + headoff;
    const float* Kh = kp + headoff;
    const float* Vh = vp + headoff;
    const int rowBase = blockIdx.x * ATM;
    const int row = rowBase + tid;

    // fill indices: 8 chunks (16B) per matrix per thread per tile
    const int fr0 = tid >> 4;          // 0..7
    const int fc  = tid & 15;          // 0..15 (16B chunk within 256B row)
    const uint32_t ksBase = smem_u32(Ks);
    const uint32_t vsBase = smem_u32(Vs);

    // q row -> registers (32 packed pairs)
    u64t q2[32];
    {
        const u64t* qr = reinterpret_cast<const u64t*>(&Q[(size_t)row * HD]);
#pragma unroll
        for (int p = 0; p < 32; p++) q2[p] = qr[p];
    }
    u64t acc[32];
#pragma unroll
    for (int d = 0; d < 32; d++) acc[d] = 0ull;
    float l = 0.f;

    // ---- async-fill tile 0 into buffer 0 ----
#pragma unroll
    for (int l2 = 0; l2 < 8; l2++) {
        int r = fr0 + 8 * l2;
        uint32_t off = (uint32_t)(r * HD + fc * 4) * 4u;   // buf 0
        cpasync16(ksBase + off, &Kh[(size_t)r * HD + fc * 4]);
        cpasync16(vsBase + off, &Vh[(size_t)r * HD + fc * 4]);
    }
    cpasync_commit();

    const int NT = S_ / ATJ;
#pragma unroll 1
    for (int t = 0; t < NT; t++) {
        const int cur = t & 1;
        const int nxt = cur ^ 1;

        cpasync_wait0();
        __syncthreads();     // tile t visible; all threads past writeout(t-1)

        // ---- async-fill next tile into alternate buffer ----
        if (t + 1 < NT) {
            const int jn = (t + 1) * ATJ;
#pragma unroll
            for (int l2 = 0; l2 < 8; l2++) {
                int r = fr0 + 8 * l2;
                uint32_t off = (uint32_t)((nxt * ATJ + r) * HD + fc * 4) * 4u;
                cpasync16(ksBase + off, &Kh[(size_t)(jn + r) * HD + fc * 4]);
                cpasync16(vsBase + off, &Vh[(size_t)(jn + r) * HD + fc * 4]);
            }
            cpasync_commit();
        }

        // ---- compute on current buffer; stage p into Ps ----
#pragma unroll 1
        for (int jj = 0; jj < ATJ; jj++) {
            // score: dot(q_row, k_jj) over 64 dims, 4-way ILP f32x2 chains
            const ulonglong2* kr = reinterpret_cast<const ulonglong2*>(
                &Ks[(size_t)(cur * ATJ + jj) * HD]);
            u64t s0 = 0ull, s1 = 0ull, s2 = 0ull, s3 = 0ull;
#pragma unroll
            for (int f = 0; f < 16; f++) {
                ulonglong2 kk = kr[f];
                if ((f & 1) == 0) { ffma2(s0, q2[2 * f], kk.x); ffma2(s1, q2[2 * f + 1], kk.y); }
                else              { ffma2(s2, q2[2 * f], kk.x); ffma2(s3, q2[2 * f + 1], kk.y); }
            }
            // packed reduction: 3 add2 + 1 unpack + 1 add
            u64t sp = add2(add2(s0, s2), add2(s1, s3));
            float sx, sy; upk2(sp, sx, sy);
            float s = sx + sy;
            float pv = __expf(s * 0.125f);   // 1/sqrt(64)
            l += pv;
            Ps[tid * PS_STRIDE + jj] = pv;   // conflict-free (65-float stride)
            u64t pp = pk2(pv, pv);
            const ulonglong2* vr = reinterpret_cast<const ulonglong2*>(
                &Vs[(size_t)(cur * ATJ + jj) * HD]);
#pragma unroll
            for (int f = 0; f < 16; f++) {
                ulonglong2 vv = vr[f];
                ffma2(acc[2 * f], pp, vv.x);
                ffma2(acc[2 * f + 1], pp, vv.y);
            }
        }
        __syncthreads();   // Ps tile complete

        // ---- coalesced writeout: 128 rows x 64 cols, 16 float4/thread.
        // lanes 0-15 cover one full row (64 cols) -> 256B segments.
        // .cs: evict-first, aw stream must not displace K/V in L2.
        {
            const int jt = t * ATJ;
#pragma unroll
            for (int i = 0; i < 16; i++) {
                int g = tid + 128 * i;          // float4 index in tile
                int r = g >> 4;                 // 0..127
                int c4 = g & 15;                // 0..15
                const float* ps = &Ps[r * PS_STRIDE + c4 * 4];
                float4 pvv = make_float4(ps[0], ps[1], ps[2], ps[3]);
                __stcs(reinterpret_cast<float4*>(
                    &aw[((size_t)bn * S_ + rowBase + r) * S_ + jt + c4 * 4]), pvv);
            }
        }
    }

    const float inv = 1.0f / l;

    // ---- x output: x[b, i, n*64+d] ----
    float* xo = xout + ((size_t)b * S_ + row) * H_ + n * HD;
#pragma unroll
    for (int d = 0; d < 32; d++) {
        float x, y; upk2(acc[d], x, y);
        *reinterpret_cast<float2*>(&xo[2 * d]) = make_float2(x * inv, y * inv);
    }

    // ---- normalize this block's own aw rows in place (fused normalize) ----
    __syncthreads();          // all writeout reads of Ps complete (race fix)
    Ps[tid] = inv;            // stage per-row scale (reuse Ps region)
    __syncthreads();
    {
        float4* awp = reinterpret_cast<float4*>(
            &aw[((size_t)bn * S_ + rowBase) * S_]);   // 128 rows x 512 float4
#pragma unroll 4
        for (int g = tid; g < ATM * (S_ / 4); g += ATM) {
            int r = g >> 9;                 // row 0..127 (512 float4 per row)
            float sc = Ps[r];
            float4 v = __ldcs(awp + g);
            v.x *= sc; v.y *= sc; v.z *= sc; v.w *= sc;
            __stcs(awp + g, v);
        }
    }
}

// =====================================================================
extern "C" void kernel_launch(void* const* d_in, const int* in_sizes, int n_in,
                              void* d_out, int out_size)
{
    const float* q  = (const float*)d_in[0];
    const float* k  = (const float*)d_in[1];
    const float* v  = (const float*)d_in[2];
    const float* Wq = (const float*)d_in[3];
    const float* Wk = (const float*)d_in[4];
    const float* Wv = (const float*)d_in[5];
    const float* Wo = (const float*)d_in[6];

    float* out = (float*)d_out;                 // [B,S,H]
    float* aw  = out + OUT_ELEMS;               // [B,NH,S,S]

    float *qp, *kp, *vp, *x;
    cudaGetSymbolAddress((void**)&qp, g_qp);
    cudaGetSymbolAddress((void**)&kp, g_kp);
    cudaGetSymbolAddress((void**)&vp, g_vp);
    cudaGetSymbolAddress((void**)&x,  g_x);

    // opt-in to >48KB dynamic smem (host-side, idempotent, capture-safe)
    cudaFuncSetAttribute(gemm_xwT, cudaFuncAttributeMaxDynamicSharedMemorySize, GEMM_SMEM);
    cudaFuncSetAttribute(attn_kernel, cudaFuncAttributeMaxDynamicSharedMemorySize, ATT_SMEM);

    // batched Q/K/V projections: grid.z = 3
    dim3 gGrid3(H_ / TN, BS_ / TM, 3);          // (8, 32, 3)
    gemm_xwT<<<gGrid3, 256, GEMM_SMEM>>>(q, Wq, qp,
                                         k, Wk, kp,
                                         v, Wv, vp,
                                         BS_, H_, H_);

    dim3 aGrid(S_ / ATM, B_ * NH);              // (16, 32)
    attn_kernel<<<aGrid, 128, ATT_SMEM>>>(qp, kp, vp, aw, x);

    // output projection
    dim3 gGrid1(H_ / TN, BS_ / TM, 1);
    gemm_xwT<<<gGrid1, 256, GEMM_SMEM>>>(x, Wo, out,
                                         x, Wo, out,
                                         x, Wo, out,
                                         BS_, H_, H_);
}